// round 11
// baseline (speedup 1.0000x reference)
#include <cuda_runtime.h>

#define BATCH   8192
#define DICTN   64
#define NDIM    8
#define MDIM    16
#define TPB     128
#define TAYLOR_D 8      // fixed sc=2 (theta<=2): apps=4, degree 8

// Two lanes per problem (partner = lane ^ 16). Lane half h owns global rows
// [4h, 4h+4). Local index trick: local slot q <-> global index q ^ 4h for both
// rows and columns -> all code warp-uniform. Each step the two lanes exchange
// their 4 updated entries via SHFL.BFLY(16).
// A[b,s] = sum_m (c[b,m]/4) * psi[m,s]  (scale 2^-2 folded into c).
// out = (TaylorExp(A) applied 4 times) @ x_block, Horner: v <- w + (A v)/k.
__global__ __launch_bounds__(TPB, 7) void transop_expm_kernel(
    const float* __restrict__ x,
    const float* __restrict__ c,
    const float* __restrict__ psi,
    float* __restrict__ out)
{
    __shared__ float psis[MDIM * 64];

    const int s    = blockIdx.y;
    const int lane = threadIdx.x & 31;
    const int warp = threadIdx.x >> 5;
    const int h    = lane >> 4;                  // which half of the problem I own
    const int b    = blockIdx.x * 64 + warp * 16 + (lane & 15);

    // Stage psi[:, s, :, :] (64 contiguous floats per m)
    for (int l = threadIdx.x; l < MDIM * 64; l += TPB) {
        const int m = l >> 6;
        const int e = l & 63;
        psis[l] = psi[(m * DICTN + s) * 64 + e];
    }
    __syncthreads();

    // c[b, :] * 0.25 (fixed 2^-2 scaling folded in; FMUL-imm)
    float cs[MDIM];
    {
        const float4* c4 = reinterpret_cast<const float4*>(c + (size_t)b * MDIM);
        #pragma unroll
        for (int q = 0; q < 4; q++) {
            float4 v = c4[q];
            cs[4*q+0] = v.x * 0.25f; cs[4*q+1] = v.y * 0.25f;
            cs[4*q+2] = v.z * 0.25f; cs[4*q+3] = v.w * 0.25f;
        }
    }

    // Build my 4 rows of A (local layout): A[il*8 + q] = A_glob[4h+il][q ^ 4h]
    // Row i=4h+il has float4s at pm[i*2 + 0] (cols 0-3) and pm[i*2 + 1] (cols 4-7).
    // Local cols 0..3 = float4 index i*2 + h; local cols 4..7 = i*2 + 1 - h.
    float A[32];
    #pragma unroll
    for (int q = 0; q < 32; q++) A[q] = 0.0f;

    #pragma unroll
    for (int m = 0; m < MDIM; m++) {
        const float cm = cs[m];
        const float4* pm = reinterpret_cast<const float4*>(&psis[m * 64]);
        #pragma unroll
        for (int il = 0; il < 4; il++) {
            const int rb = (4*h + il) * 2;
            float4 pa = pm[rb + h];        // local cols 0..3 (LDS.128, dual-broadcast)
            float4 pb = pm[rb + 1 - h];    // local cols 4..7
            A[il*8+0] = fmaf(cm, pa.x, A[il*8+0]);
            A[il*8+1] = fmaf(cm, pa.y, A[il*8+1]);
            A[il*8+2] = fmaf(cm, pa.z, A[il*8+2]);
            A[il*8+3] = fmaf(cm, pa.w, A[il*8+3]);
            A[il*8+4] = fmaf(cm, pb.x, A[il*8+4]);
            A[il*8+5] = fmaf(cm, pb.y, A[il*8+5]);
            A[il*8+6] = fmaf(cm, pb.z, A[il*8+6]);
            A[il*8+7] = fmaf(cm, pb.w, A[il*8+7]);
        }
    }

    // Load x block in local order: v[0..3] = my rows (float4 at +4h),
    // v[4..7] = partner rows (float4 at +4(1-h)).
    float v[8];
    {
        const float4* xb = reinterpret_cast<const float4*>(x + (size_t)b * (DICTN*NDIM) + s * NDIM);
        float4 xa = xb[h];
        float4 xo = xb[1 - h];
        v[0]=xa.x; v[1]=xa.y; v[2]=xa.z; v[3]=xa.w;
        v[4]=xo.x; v[5]=xo.y; v[6]=xo.z; v[7]=xo.w;
    }

    // apps = 4 (fixed), degree-8 Horner per app
    #pragma unroll
    for (int a = 0; a < 4; a++) {
        float wa[4];
        #pragma unroll
        for (int q = 0; q < 4; q++) wa[q] = v[q];   // my slots at app entry

        #pragma unroll
        for (int k = TAYLOR_D; k >= 1; k--) {
            const float invk = 1.0f / (float)k;     // compile-time -> FFMA-imm (rt=1)
            float vn[4];
            #pragma unroll
            for (int il = 0; il < 4; il++) {
                float r = A[il*8 + 0] * v[0];
                #pragma unroll
                for (int j = 1; j < 8; j++) r = fmaf(A[il*8 + j], v[j], r);
                vn[il] = fmaf(invk, r, wa[il]);      // v <- w + (A v)/k
            }
            // Exchange halves with partner lane (skip at the very end: store
            // needs only my slots)
            if (!(a == 3 && k == 1)) {
                #pragma unroll
                for (int q = 0; q < 4; q++) {
                    v[4+q] = __shfl_xor_sync(0xffffffffu, vn[q], 16);
                    v[q]   = vn[q];
                }
            } else {
                #pragma unroll
                for (int q = 0; q < 4; q++) v[q] = vn[q];
            }
        }
    }

    // Store my 4 entries (lanes l and l^16 write adjacent float4s)
    {
        float4* ob = reinterpret_cast<float4*>(out + (size_t)b * (DICTN*NDIM) + s * NDIM);
        ob[h] = make_float4(v[0], v[1], v[2], v[3]);
    }
}

extern "C" void kernel_launch(void* const* d_in, const int* in_sizes, int n_in,
                              void* d_out, int out_size) {
    const float* x   = (const float*)d_in[0];   // (B, 512)
    const float* c   = (const float*)d_in[1];   // (B, 16)
    const float* psi = (const float*)d_in[2];   // (16, 64, 8, 8)
    float* out = (float*)d_out;                 // (B, 512)

    dim3 grid(BATCH / 64, DICTN);               // (128, 64): 2 lanes per (b,s)
    transop_expm_kernel<<<grid, TPB>>>(x, c, psi, out);
}